// round 2
// baseline (speedup 1.0000x reference)
#include <cuda_runtime.h>

// ISTFT = folded-Hermitian SGEMM + overlap-add + wss normalize.
// Shapes (fixed by the dataset): B=8, T=1000, F=1025, NFFT=2048, HOP=512.

#define NFFT   2048
#define FREQ   1025
#define HOPLEN 512
#define BATCH  8
#define KTOT   (2 * FREQ)   // 2050

// Scratch (static __device__ arrays: the sanctioned no-alloc workaround).
__device__ float g_afold[KTOT * NFFT];          // [k][o], 16.8 MB
__device__ float g_s[BATCH * 1000 * NFFT];      // [b*nf + t][o], 65.5 MB

// ---------------------------------------------------------------------------
// Kernel 1: fold Hermitian symmetry into the IDFT weights.
// Afold[k][o]      = Wr[o][k] + (1<=k<=1023 ? Wr[o][2048-k] : 0)        (k < 1025)
// Afold[1025+k][o] = -Wi[o][k] + (1<=k<=1023 ? Wi[o][2048-k] : 0)
// ---------------------------------------------------------------------------
__global__ void fold_kernel(const float* __restrict__ Wr,
                            const float* __restrict__ Wi) {
    int o = blockIdx.x * blockDim.x + threadIdx.x;   // 0..2047 (coalesced writes)
    int k = blockIdx.y;                              // 0..2049
    if (o >= NFFT) return;
    float v;
    if (k < FREQ) {
        v = Wr[(size_t)o * NFFT + k];
        if (k >= 1 && k <= NFFT / 2 - 1) v += Wr[(size_t)o * NFFT + (NFFT - k)];
    } else {
        int kk = k - FREQ;
        v = -Wi[(size_t)o * NFFT + kk];
        if (kk >= 1 && kk <= NFFT / 2 - 1) v += Wi[(size_t)o * NFFT + (NFFT - kk)];
    }
    g_afold[(size_t)k * NFFT + o] = v;
}

// ---------------------------------------------------------------------------
// Kernel 2: SGEMM  s[m][o] = sum_k X[m][k] * Afold[k][o]
//   m in [0, B*nf), X[m][k] = (k<1025) ? Xr[xrow][k] : Xi[xrow][k-1025]
// Block tile 128x128, K-tile 8, 256 threads, 8x8 microtile.
// ---------------------------------------------------------------------------
__global__ void __launch_bounds__(256)
gemm_kernel(const float* __restrict__ Xr, const float* __restrict__ Xi,
            int T, int nf) {
    const int Mtot = BATCH * nf;
    __shared__ float As[8][128];
    __shared__ float Bs[8][128];

    const int tid = threadIdx.x;
    const int tx  = tid & 15;        // 0..15 -> n microtile
    const int ty  = tid >> 4;        // 0..15 -> m microtile
    const int m0  = blockIdx.y * 128;
    const int n0  = blockIdx.x * 128;

    // A-tile load assignment: each thread owns one row, 4 consecutive k.
    const int rowA  = tid >> 1;            // 0..127
    const int kbase = (tid & 1) * 4;       // 0 or 4
    const int gm    = m0 + rowA;
    const bool rowOk = (gm < Mtot);
    int xrow = 0;
    if (rowOk) {
        int b = gm / nf;
        int t = gm - b * nf;
        xrow = b * T + t;
    }
    const size_t xbase = (size_t)xrow * FREQ;

    // B-tile load assignment: one float4 per thread.
    const int kb = tid >> 5;               // 0..7
    const int nb = (tid & 31) * 4;         // 0..124

    float acc[8][8];
#pragma unroll
    for (int i = 0; i < 8; i++)
#pragma unroll
        for (int j = 0; j < 8; j++) acc[i][j] = 0.f;

    for (int k0 = 0; k0 < KTOT; k0 += 8) {
        __syncthreads();
        // --- load A tile (transposed into As[k][m]) ---
#pragma unroll
        for (int i = 0; i < 4; i++) {
            int kg = k0 + kbase + i;
            float v = 0.f;
            if (rowOk && kg < KTOT) {
                v = (kg < FREQ) ? Xr[xbase + kg] : Xi[xbase + (kg - FREQ)];
            }
            As[kbase + i][rowA] = v;
        }
        // --- load B tile (coalesced float4) ---
        float4 bv = make_float4(0.f, 0.f, 0.f, 0.f);
        if (k0 + kb < KTOT) {
            bv = *(const float4*)&g_afold[(size_t)(k0 + kb) * NFFT + n0 + nb];
        }
        *(float4*)&Bs[kb][nb] = bv;
        __syncthreads();

        // --- compute ---
#pragma unroll
        for (int kk = 0; kk < 8; kk++) {
            float a[8], bb[8];
            *(float4*)&a[0]  = *(const float4*)&As[kk][ty * 8];
            *(float4*)&a[4]  = *(const float4*)&As[kk][ty * 8 + 4];
            *(float4*)&bb[0] = *(const float4*)&Bs[kk][tx * 8];
            *(float4*)&bb[4] = *(const float4*)&Bs[kk][tx * 8 + 4];
#pragma unroll
            for (int i = 0; i < 8; i++)
#pragma unroll
                for (int j = 0; j < 8; j++)
                    acc[i][j] += a[i] * bb[j];
        }
    }

    // --- epilogue ---
#pragma unroll
    for (int i = 0; i < 8; i++) {
        int m = m0 + ty * 8 + i;
        if (m < Mtot) {
            float* dst = &g_s[(size_t)m * NFFT + n0 + tx * 8];
            *(float4*)&dst[0] = make_float4(acc[i][0], acc[i][1], acc[i][2], acc[i][3]);
            *(float4*)&dst[4] = make_float4(acc[i][4], acc[i][5], acc[i][6], acc[i][7]);
        }
    }
}

// ---------------------------------------------------------------------------
// Kernel 3: overlap-add + window-sumsquare normalization.
// out[b][q] for q in [0,length): p = q + NFFT/2; sum over frames t with
// 0 <= p - t*HOP < NFFT  (at most 4 frames), divide by wss (guarded).
// ---------------------------------------------------------------------------
__global__ void oa_kernel(const float* __restrict__ win,
                          float* __restrict__ out,
                          int nf, int length) {
    int idx = blockIdx.x * blockDim.x + threadIdx.x;
    if (idx >= BATCH * length) return;
    int b = idx / length;
    int p = (idx - b * length) + NFFT / 2;

    int thi = p >> 9;                    // p / HOP
    int tlo = thi - 3; if (tlo < 0) tlo = 0;
    int tup = thi;     if (tup > nf - 1) tup = nf - 1;

    float acc = 0.f, wss = 0.f;
    for (int t = tlo; t <= tup; t++) {
        int o = p - (t << 9);            // guaranteed in [0, 2048)
        float w = win[o];
        wss += w * w;
        acc += g_s[((size_t)(b * nf + t)) * NFFT + o];
    }
    // jnp.finfo(float32).tiny
    out[idx] = (wss > 1.17549435e-38f) ? (acc / wss) : acc;
}

// ---------------------------------------------------------------------------
extern "C" void kernel_launch(void* const* d_in, const int* in_sizes, int n_in,
                              void* d_out, int out_size) {
    const float* real_stft = (const float*)d_in[0];  // (8,1,T,1025)
    const float* imag_stft = (const float*)d_in[1];
    const float* W_real    = (const float*)d_in[2];  // (2048,2048) [o][i]
    const float* W_imag    = (const float*)d_in[3];
    const float* window    = (const float*)d_in[4];  // (2048,)
    // d_in[5] = length (device scalar; derive host-side instead)

    const int T      = in_sizes[0] / (BATCH * FREQ);       // 1000
    const int length = out_size / BATCH;                   // 511488
    int nf = (length + NFFT + HOPLEN - 1) / HOPLEN;        // ceil((len+nfft)/hop)
    if (nf > T) nf = T;                                    // -> 1000

    // 1) fold weights
    {
        dim3 grid(NFFT / 256, KTOT);
        fold_kernel<<<grid, 256>>>(W_real, W_imag);
    }
    // 2) GEMM
    {
        const int Mtot = BATCH * nf;
        dim3 grid(NFFT / 128, (Mtot + 127) / 128);
        gemm_kernel<<<grid, 256>>>(real_stft, imag_stft, T, nf);
    }
    // 3) overlap-add + normalize
    {
        int total = BATCH * length;
        oa_kernel<<<(total + 255) / 256, 256>>>(window, (float*)d_out, nf, length);
    }
}

// round 7
// speedup vs baseline: 4.2426x; 4.2426x over previous
#include <cuda_runtime.h>
#include <cuda_bf16.h>
#include <cstdint>

// ISTFT on GB300 (harness PTX target is plain sm_103 -> no tcgen05; use
// legacy mma.sync bf16 HMMA path, which is not 'a'-feature gated).
//
// Pipeline: pack X/B into hi/lo bf16 (compensated split, 3-product GEMM)
//           -> TN mma.sync GEMM (128x128 block, cp.async double buffer)
//           -> overlap-add + window-sumsquare normalize.
// Shapes: B=8, T=1000, F=1025, NFFT=2048, HOP=512, K=2050 (pad 2112).

#define NFFT   2048
#define FREQ   1025
#define HOPLEN 512
#define BATCH  8
#define KTOT   2050
#define KPAD   2112            // 66 * 32
#define MPAD   8064            // 63 * 128
#define KSTAGE 32
#define NSTAGE 66
#define ROWB   80              // smem row stride in bytes (40 halves) - conflict free
#define MATB   10240           // 128 rows * 80 B per matrix tile
#define BUFB   40960           // Ah|Al|Bh|Bl per stage
#define SMEM_TOTAL (2 * BUFB)

// ---------------- scratch (static device arrays; no allocs) ----------------
__device__ __align__(256) __nv_bfloat16 g_Xh[(size_t)MPAD * KPAD];
__device__ __align__(256) __nv_bfloat16 g_Xl[(size_t)MPAD * KPAD];
__device__ __align__(256) __nv_bfloat16 g_Bh[(size_t)NFFT * KPAD];
__device__ __align__(256) __nv_bfloat16 g_Bl[(size_t)NFFT * KPAD];
__device__ __align__(256) float         g_s [(size_t)MPAD * NFFT];

// ---------------- PTX helpers ----------------
__device__ __forceinline__ void cpa16(uint32_t dst, const void* src) {
    asm volatile("cp.async.cg.shared.global [%0], [%1], 16;\n" :: "r"(dst), "l"(src));
}
__device__ __forceinline__ void ldsm4(uint32_t* r, uint32_t addr) {
    asm volatile("ldmatrix.sync.aligned.m8n8.x4.shared.b16 {%0,%1,%2,%3}, [%4];"
                 : "=r"(r[0]), "=r"(r[1]), "=r"(r[2]), "=r"(r[3]) : "r"(addr));
}
__device__ __forceinline__ void mma16816(float* d, const uint32_t* a, const uint32_t* b) {
    asm volatile(
        "mma.sync.aligned.m16n8k16.row.col.f32.bf16.bf16.f32 "
        "{%0,%1,%2,%3}, {%4,%5,%6,%7}, {%8,%9}, {%0,%1,%2,%3};"
        : "+f"(d[0]), "+f"(d[1]), "+f"(d[2]), "+f"(d[3])
        : "r"(a[0]), "r"(a[1]), "r"(a[2]), "r"(a[3]), "r"(b[0]), "r"(b[1]));
}

// ---------------- kernel 1: pack X into hi/lo bf16 (Hermitian-indexed) ------
__global__ void __launch_bounds__(256)
pack_x(const float* __restrict__ re, const float* __restrict__ im, int T, int nf) {
    size_t idx = (size_t)blockIdx.x * 256 + threadIdx.x;
    if (idx >= (size_t)MPAD * KPAD) return;
    int m = (int)(idx / KPAD);
    int k = (int)(idx - (size_t)m * KPAD);
    float v = 0.f;
    if (m < BATCH * nf && k < KTOT) {
        int b = m / nf, t = m - b * nf;
        size_t row = (size_t)(b * T + t) * FREQ;
        v = (k < FREQ) ? re[row + k] : im[row + (k - FREQ)];
    }
    __nv_bfloat16 h = __float2bfloat16(v);
    g_Xh[idx] = h;
    g_Xl[idx] = __float2bfloat16(v - __bfloat162float(h));
}

// ---------------- kernel 2: fold Hermitian into B, hi/lo bf16 ---------------
__global__ void __launch_bounds__(256)
pack_b(const float* __restrict__ Wr, const float* __restrict__ Wi) {
    size_t idx = (size_t)blockIdx.x * 256 + threadIdx.x;
    if (idx >= (size_t)NFFT * KPAD) return;
    int n = (int)(idx / KPAD);
    int k = (int)(idx - (size_t)n * KPAD);
    float v = 0.f;
    if (k < KTOT) {
        if (k < FREQ) {
            v = Wr[(size_t)n * NFFT + k];
            if (k >= 1 && k <= NFFT / 2 - 1) v += Wr[(size_t)n * NFFT + (NFFT - k)];
        } else {
            int kk = k - FREQ;
            v = -Wi[(size_t)n * NFFT + kk];
            if (kk >= 1 && kk <= NFFT / 2 - 1) v += Wi[(size_t)n * NFFT + (NFFT - kk)];
        }
    }
    __nv_bfloat16 h = __float2bfloat16(v);
    g_Bh[idx] = h;
    g_Bl[idx] = __float2bfloat16(v - __bfloat162float(h));
}

// ---------------- kernel 3: TN bf16 mma.sync GEMM ---------------------------
// s[m][n] = sum_k X[m][k] * B[n][k],  X = Xh+Xl, B = Bh+Bl (drop Xl*Bl).
__device__ __forceinline__ void load_stage(int s, uint32_t smem_base,
                                           int m0, int n0, int tid) {
    const int k0 = s * KSTAGE;
    const uint32_t buf = smem_base + (uint32_t)(s & 1) * BUFB;
#pragma unroll
    for (int i = 0; i < 8; i++) {
        const int mat = i >> 1;                       // 0 Xh, 1 Xl, 2 Bh, 3 Bl
        const int off = ((i & 1) << 8) + tid;         // 0..511 within matrix
        const int r = off >> 2, c = off & 3;
        const int rowbase = (mat < 2 ? m0 : n0) + r;
        const __nv_bfloat16* src =
            (mat == 0 ? g_Xh : mat == 1 ? g_Xl : mat == 2 ? g_Bh : g_Bl);
        cpa16(buf + (uint32_t)(mat * MATB + r * ROWB + c * 16),
              src + (size_t)rowbase * KPAD + k0 + c * 8);
    }
    asm volatile("cp.async.commit_group;\n" ::: "memory");
}

__global__ void __launch_bounds__(256)
gemm_mma() {
    extern __shared__ char smem[];
    const uint32_t smem_base = (uint32_t)__cvta_generic_to_shared(smem);
    const int tid  = threadIdx.x;
    const int lane = tid & 31;
    const int wid  = tid >> 5;
    const int warpM = (wid & 3) * 32;     // 4 warps over m
    const int warpN = (wid >> 2) * 64;    // 2 warps over n
    const int m0 = blockIdx.y * 128;
    const int n0 = blockIdx.x * 128;

    // ldmatrix per-lane address components (group g = lane>>3)
    const int g = lane >> 3;
    // A: groups -> (m+0,k+0),(m+8,k+0),(m+0,k+8),(m+8,k+8)
    const uint32_t aRowOff =
        (uint32_t)((warpM + ((g & 1) << 3) + (lane & 7)) * ROWB + ((g >> 1) << 4));
    // B: groups -> (n+0,k+0),(n+0,k+8),(n+8,k+0),(n+8,k+8)
    const uint32_t bRowOff =
        (uint32_t)((warpN + (((g >> 1) & 1) << 3) + (lane & 7)) * ROWB + ((g & 1) << 4));

    float acc[2][8][4];
#pragma unroll
    for (int i = 0; i < 2; i++)
#pragma unroll
        for (int j = 0; j < 8; j++)
#pragma unroll
            for (int q = 0; q < 4; q++) acc[i][j][q] = 0.f;

    load_stage(0, smem_base, m0, n0, tid);

    for (int s = 0; s < NSTAGE; s++) {
        if (s + 1 < NSTAGE) {
            load_stage(s + 1, smem_base, m0, n0, tid);
            asm volatile("cp.async.wait_group 1;\n" ::: "memory");
        } else {
            asm volatile("cp.async.wait_group 0;\n" ::: "memory");
        }
        __syncthreads();

        const uint32_t buf = smem_base + (uint32_t)(s & 1) * BUFB;
#pragma unroll
        for (int ks = 0; ks < 2; ks++) {
            uint32_t a_h[2][4], a_l[2][4];
            {
                uint32_t ao = buf + aRowOff + (uint32_t)(ks * 32);
                ldsm4(a_h[0], ao);
                ldsm4(a_h[1], ao + 1280);
                ldsm4(a_l[0], ao + MATB);
                ldsm4(a_l[1], ao + MATB + 1280);
            }
            uint32_t b_h[8][2], b_l[8][2];
            {
                uint32_t bo = buf + 2 * MATB + bRowOff + (uint32_t)(ks * 32);
#pragma unroll
                for (int p = 0; p < 4; p++) {
                    uint32_t t[4];
                    ldsm4(t, bo + (uint32_t)(p * 1280));
                    b_h[2 * p][0] = t[0]; b_h[2 * p][1] = t[1];
                    b_h[2 * p + 1][0] = t[2]; b_h[2 * p + 1][1] = t[3];
                    ldsm4(t, bo + MATB + (uint32_t)(p * 1280));
                    b_l[2 * p][0] = t[0]; b_l[2 * p][1] = t[1];
                    b_l[2 * p + 1][0] = t[2]; b_l[2 * p + 1][1] = t[3];
                }
            }
#pragma unroll
            for (int fm = 0; fm < 2; fm++)
#pragma unroll
                for (int fn = 0; fn < 8; fn++) {
                    mma16816(acc[fm][fn], a_h[fm], b_h[fn]);
                    mma16816(acc[fm][fn], a_l[fm], b_h[fn]);
                    mma16816(acc[fm][fn], a_h[fm], b_l[fn]);
                }
        }
        __syncthreads();
    }

    // Epilogue: C frag -> g_s (row = lane/4 (+8), col pair = 2*(lane%4))
#pragma unroll
    for (int fm = 0; fm < 2; fm++) {
        const int row = m0 + warpM + fm * 16 + (lane >> 2);
#pragma unroll
        for (int fn = 0; fn < 8; fn++) {
            const int col = n0 + warpN + fn * 8 + ((lane & 3) << 1);
            float* p = &g_s[(size_t)row * NFFT + col];
            *(float2*)p = make_float2(acc[fm][fn][0], acc[fm][fn][1]);
            *(float2*)(p + 8 * NFFT) = make_float2(acc[fm][fn][2], acc[fm][fn][3]);
        }
    }
}

// ---------------- kernel 4: overlap-add + wss normalize ---------------------
__global__ void __launch_bounds__(256)
oa_kernel(const float* __restrict__ win, float* __restrict__ out,
          int nf, int length) {
    int idx = blockIdx.x * blockDim.x + threadIdx.x;
    if (idx >= BATCH * length) return;
    int b = idx / length;
    int p = (idx - b * length) + NFFT / 2;

    int thi = p >> 9;
    int tlo = thi - 3; if (tlo < 0) tlo = 0;
    int tup = thi;     if (tup > nf - 1) tup = nf - 1;

    float acc = 0.f, wss = 0.f;
    for (int t = tlo; t <= tup; t++) {
        int o = p - (t << 9);
        float w = win[o];
        wss += w * w;
        acc += g_s[((size_t)(b * nf + t)) * NFFT + o];
    }
    out[idx] = (wss > 1.17549435e-38f) ? (acc / wss) : acc;
}

// ---------------------------------------------------------------------------
extern "C" void kernel_launch(void* const* d_in, const int* in_sizes, int n_in,
                              void* d_out, int out_size) {
    const float* real_stft = (const float*)d_in[0];
    const float* imag_stft = (const float*)d_in[1];
    const float* W_real    = (const float*)d_in[2];
    const float* W_imag    = (const float*)d_in[3];
    const float* window    = (const float*)d_in[4];

    const int T      = in_sizes[0] / (BATCH * FREQ);        // 1000
    const int length = out_size / BATCH;                    // 511488
    int nf = (length + NFFT + HOPLEN - 1) / HOPLEN;
    if (nf > T) nf = T;                                     // 1000

    // 1) pack X (hi/lo bf16, Hermitian-indexed, zero-padded)
    {
        size_t total = (size_t)MPAD * KPAD;
        pack_x<<<(unsigned)((total + 255) / 256), 256>>>(real_stft, imag_stft, T, nf);
    }
    // 2) pack folded B (hi/lo bf16)
    {
        size_t total = (size_t)NFFT * KPAD;
        pack_b<<<(unsigned)((total + 255) / 256), 256>>>(W_real, W_imag);
    }
    // 3) mma.sync GEMM
    {
        static bool attr_set = false;
        if (!attr_set) {
            cudaFuncSetAttribute(gemm_mma, cudaFuncAttributeMaxDynamicSharedMemorySize,
                                 SMEM_TOTAL);
            attr_set = true;
        }
        dim3 grid(NFFT / 128, MPAD / 128);                  // (16, 63)
        gemm_mma<<<grid, 256, SMEM_TOTAL>>>();
    }
    // 4) overlap-add + normalize
    {
        int total = BATCH * length;
        oa_kernel<<<(total + 255) / 256, 256>>>(window, (float*)d_out, nf, length);
    }
}